// round 4
// baseline (speedup 1.0000x reference)
#include <cuda_runtime.h>
#include <cstdint>

#define BB   256
#define TT   256
#define MM   8
#define AUXD 32
#define HH   64
#define BT   (BB*TT)

// Scratch: r (softmaxed redistribution matrices) and j (softmaxed junction probs)
__device__ float g_r[(unsigned long long)BT * 4096ull];  // [bt][h*64+k]
__device__ float g_j[(unsigned long long)BT * 512ull];   // [bt][m*64+h]

// ---------------- packed f32x2 helpers ----------------
__device__ __forceinline__ void fma2(unsigned long long& d, unsigned long long a, unsigned long long b) {
    asm("fma.rn.f32x2 %0, %1, %2, %0;" : "+l"(d) : "l"(a), "l"(b));
}
__device__ __forceinline__ unsigned long long splat2(float a) {
    unsigned long long r;
    asm("mov.b64 %0, {%1, %1};" : "=l"(r) : "f"(a));
    return r;
}

// ---------------- Phase 1: GEMM [BT,32]x[32,N] + bias + groupwise(64) softmax ----------------
// Tile: 64 rows x 256 cols, 256 threads. ty=tid/32 (row group), tx=tid%32.
// Thread owns rows {ty+8i, i<8}, col pairs {2tx+64j, j<4}  -> softmax group j is exactly one warp.
__global__ __launch_bounds__(256, 2)
void gemm_softmax_kernel(const float* __restrict__ A,    // [BT,32]
                         const float* __restrict__ W,    // [32,N]
                         const float* __restrict__ bias, // [N]
                         float* __restrict__ out,        // [BT,N]
                         int N)
{
    __shared__ __align__(16) float Ast[32][65];   // transposed A tile (padded)
    __shared__ __align__(16) float Bs[32][256];

    const int tid = threadIdx.x;
    const int tx  = tid & 31;
    const int ty  = tid >> 5;
    const int row0 = blockIdx.y * 64;
    const int c0   = blockIdx.x * 256;

    // Load A tile (64x32) transposed into Ast
    #pragma unroll
    for (int q = 0; q < 2; q++) {
        int i4 = q * 256 + tid;            // 512 float4 total
        int r  = i4 >> 3;                  // 8 float4 per row
        int cc = (i4 & 7) * 4;
        float4 v = *(const float4*)(A + (size_t)(row0 + r) * 32 + cc);
        Ast[cc + 0][r] = v.x; Ast[cc + 1][r] = v.y;
        Ast[cc + 2][r] = v.z; Ast[cc + 3][r] = v.w;
    }
    // Load B tile (32 x 256)
    #pragma unroll
    for (int q = 0; q < 8; q++) {
        int i4 = q * 256 + tid;            // 2048 float4 total
        int r  = i4 >> 6;                  // 64 float4 per row
        int cc = (i4 & 63) * 4;
        float4 v = *(const float4*)(W + (size_t)r * N + c0 + cc);
        *(float4*)&Bs[r][cc] = v;
    }
    __syncthreads();

    const int colb = 2 * tx;
    unsigned long long acc[8][4];
    #pragma unroll
    for (int i = 0; i < 8; i++)
        #pragma unroll
        for (int j = 0; j < 4; j++) acc[i][j] = 0ull;

    #pragma unroll 4
    for (int k = 0; k < 32; k++) {
        unsigned long long b0 = *(const unsigned long long*)&Bs[k][colb];
        unsigned long long b1 = *(const unsigned long long*)&Bs[k][colb + 64];
        unsigned long long b2 = *(const unsigned long long*)&Bs[k][colb + 128];
        unsigned long long b3 = *(const unsigned long long*)&Bs[k][colb + 192];
        #pragma unroll
        for (int i = 0; i < 8; i++) {
            unsigned long long av = splat2(Ast[k][ty + 8 * i]);
            fma2(acc[i][0], av, b0);
            fma2(acc[i][1], av, b1);
            fma2(acc[i][2], av, b2);
            fma2(acc[i][3], av, b3);
        }
    }

    // bias
    float2 bv[4];
    #pragma unroll
    for (int j = 0; j < 4; j++)
        bv[j] = *(const float2*)(bias + c0 + colb + 64 * j);

    // exp + group softmax (group = one warp) + store
    #pragma unroll
    for (int i = 0; i < 8; i++) {
        int row = row0 + ty + 8 * i;
        #pragma unroll
        for (int j = 0; j < 4; j++) {
            float2 e = *(float2*)&acc[i][j];
            e.x = __expf(e.x + bv[j].x);
            e.y = __expf(e.y + bv[j].y);
            float s = e.x + e.y;
            s += __shfl_xor_sync(0xffffffffu, s, 16);
            s += __shfl_xor_sync(0xffffffffu, s, 8);
            s += __shfl_xor_sync(0xffffffffu, s, 4);
            s += __shfl_xor_sync(0xffffffffu, s, 2);
            s += __shfl_xor_sync(0xffffffffu, s, 1);
            float rinv = 1.0f / s;
            e.x *= rinv; e.y *= rinv;
            *(float2*)(out + (size_t)row * N + c0 + colb + 64 * j) = e;
        }
    }
}

// ---------------- Phase 2: per-batch recurrence ----------------
__device__ __forceinline__ void cpasync16(void* smem, const void* g) {
    unsigned s = (unsigned)__cvta_generic_to_shared(smem);
    asm volatile("cp.async.cg.shared.global [%0], [%1], 16;" :: "r"(s), "l"(g));
}
#define CP_COMMIT()  asm volatile("cp.async.commit_group;")
#define CP_WAIT1()   asm volatile("cp.async.wait_group 1;")

__global__ __launch_bounds__(256, 2)
void recur_kernel(const float* __restrict__ xm,   // [B,T,8]
                  const float* __restrict__ xa,   // [B,T,32]
                  const float* __restrict__ Wo,   // [32,64]
                  const float* __restrict__ bo,   // [64]
                  const float* __restrict__ Wfc,  // [64,1]
                  const float* __restrict__ bfc,  // [1]
                  float* __restrict__ d_out,
                  int out_size)
{
    const int b   = blockIdx.x;
    const int tid = threadIdx.x;

    __shared__ __align__(16) float rbuf[2][4096];
    __shared__ __align__(16) float jbuf[2][512];
    __shared__ __align__(16) float mbuf[2][8];
    __shared__ float c_s[64];
    __shared__ float psum[256];
    __shared__ float xa_s[32];

    if (tid < 64) c_s[tid] = 0.0f;
    if (tid < 32) xa_s[tid] = xa[((size_t)b * TT + (TT - 1)) * AUXD + tid];

    // prologue load of stage 0
    {
        const float* rsrc = g_r + ((size_t)(b * TT + 0) << 12);
        #pragma unroll
        for (int q = 0; q < 4; q++)
            cpasync16(&rbuf[0][q * 1024 + tid * 4], rsrc + q * 1024 + tid * 4);
        if (tid < 128) {
            const float* jsrc = g_j + ((size_t)(b * TT + 0) << 9);
            cpasync16(&jbuf[0][tid * 4], jsrc + tid * 4);
        }
        if (tid < 2) {
            const float* msrc = xm + ((size_t)(b * TT + 0) << 3);
            cpasync16(&mbuf[0][tid * 4], msrc + tid * 4);
        }
    }
    CP_COMMIT();

    const int k = tid & 63;
    const int p = tid >> 6;

    for (int t = 0; t < TT; t++) {
        const int s = t & 1;
        if (t + 1 < TT) {
            const int s2 = (t + 1) & 1;
            const float* rsrc = g_r + ((size_t)(b * TT + t + 1) << 12);
            #pragma unroll
            for (int q = 0; q < 4; q++)
                cpasync16(&rbuf[s2][q * 1024 + tid * 4], rsrc + q * 1024 + tid * 4);
            if (tid < 128) {
                const float* jsrc = g_j + ((size_t)(b * TT + t + 1) << 9);
                cpasync16(&jbuf[s2][tid * 4], jsrc + tid * 4);
            }
            if (tid < 2) {
                const float* msrc = xm + ((size_t)(b * TT + t + 1) << 3);
                cpasync16(&mbuf[s2][tid * 4], msrc + tid * 4);
            }
        }
        CP_COMMIT();
        CP_WAIT1();          // stage s is complete
        __syncthreads();

        // m_sys partials: part p covers h in [16p, 16p+16)
        const float* rs = rbuf[s];
        float acc = 0.0f;
        #pragma unroll
        for (int hh = 0; hh < 16; hh++) {
            int h = 16 * p + hh;
            acc += c_s[h] * rs[h * 64 + k];
        }
        psum[tid] = acc;
        __syncthreads();

        if (tid < 64) {
            float m_in = 0.0f;
            #pragma unroll
            for (int m = 0; m < 8; m++)
                m_in += mbuf[s][m] * jbuf[s][m * 64 + k];
            float cn = m_in + psum[k] + psum[64 + k] + psum[128 + k] + psum[192 + k];
            c_s[k] = cn;
        }
        __syncthreads();
    }

    // Epilogue: o = sigmoid(xa_last @ Wo + bo); a = o*c; out = a @ Wfc + bfc
    if (tid < 64) {
        float dot = bo[tid];
        #pragma unroll
        for (int a = 0; a < 32; a++)
            dot += xa_s[a] * Wo[a * 64 + tid];
        float o = 1.0f / (1.0f + __expf(-dot));
        float aout = o * c_s[tid];
        float v = aout * Wfc[tid];
        v += __shfl_xor_sync(0xffffffffu, v, 16);
        v += __shfl_xor_sync(0xffffffffu, v, 8);
        v += __shfl_xor_sync(0xffffffffu, v, 4);
        v += __shfl_xor_sync(0xffffffffu, v, 2);
        v += __shfl_xor_sync(0xffffffffu, v, 1);
        if ((tid & 31) == 0) psum[tid >> 5] = v;
    }
    __syncthreads();

    if (tid == 0) d_out[b] = psum[0] + psum[1] + bfc[0];
    if (tid < 64 && out_size >= BB + BB * HH)
        d_out[BB + b * HH + tid] = c_s[tid];   // c_final
}

// ---------------- launch ----------------
extern "C" void kernel_launch(void* const* d_in, const int* in_sizes, int n_in,
                              void* d_out, int out_size) {
    const float* x_m = (const float*)d_in[0];
    const float* x_a = (const float*)d_in[1];
    const float* Wj  = (const float*)d_in[2];
    const float* bj  = (const float*)d_in[3];
    const float* Wr  = (const float*)d_in[4];
    const float* br  = (const float*)d_in[5];
    const float* Wo  = (const float*)d_in[6];
    const float* bo  = (const float*)d_in[7];
    const float* Wfc = (const float*)d_in[8];
    const float* bfc = (const float*)d_in[9];
    float* out = (float*)d_out;

    void* pj = nullptr;
    void* pr = nullptr;
    cudaGetSymbolAddress(&pj, g_j);
    cudaGetSymbolAddress(&pr, g_r);

    // j: softmax((xa @ Wj + bj) grouped by 64)  -> g_j [BT,512]
    gemm_softmax_kernel<<<dim3(2, BT / 64), 256>>>(x_a, Wj, bj, (float*)pj, 512);
    // r: softmax((xa @ Wr + br) grouped by 64)  -> g_r [BT,4096]
    gemm_softmax_kernel<<<dim3(16, BT / 64), 256>>>(x_a, Wr, br, (float*)pr, 4096);
    // scan
    recur_kernel<<<BB, 256>>>(x_m, x_a, Wo, bo, Wfc, bfc, out, out_size);
}

// round 7
// speedup vs baseline: 1.4355x; 1.4355x over previous
#include <cuda_runtime.h>
#include <cuda_bf16.h>
#include <cstdint>

#define BB   256
#define TT   256
#define MM   8
#define AUXD 32
#define HH   64
#define BT   (BB*TT)

// ---------------- global scratch ----------------
__device__ float g_r[(unsigned long long)BT * 4096ull];  // [bt][h*64+k]  softmaxed
__device__ float g_j[(unsigned long long)BT * 512ull];   // [bt][m*64+h]  softmaxed
// bf16-split images for mma.sync
__device__ __nv_bfloat16 g_a[(unsigned long long)BT * 64ull];  // [bt][64]: [a_hi(32)|a_lo(32)]
__device__ __nv_bfloat16 g_br[4096 * 96];   // [n][96]: [w_hi|w_hi|w_lo]
__device__ __nv_bfloat16 g_bj[512 * 96];

// ---------------- helpers ----------------
__device__ __forceinline__ uint32_t smem_u32(const void* p) {
    uint32_t a;
    asm("{ .reg .u64 t; cvta.to.shared.u64 t, %1; cvt.u32.u64 %0, t; }" : "=r"(a) : "l"(p));
    return a;
}
__device__ __forceinline__ void cpasync16(uint32_t smem, const void* g) {
    asm volatile("cp.async.cg.shared.global [%0], [%1], 16;" :: "r"(smem), "l"(g));
}
#define CP_COMMIT()  asm volatile("cp.async.commit_group;")
#define CP_WAIT0()   asm volatile("cp.async.wait_group 0;")
#define CP_WAIT1()   asm volatile("cp.async.wait_group 1;")

__device__ __forceinline__ void mma16816(float* c, uint32_t a0, uint32_t a1, uint32_t a2,
                                         uint32_t a3, uint32_t b0, uint32_t b1) {
    asm volatile(
        "mma.sync.aligned.m16n8k16.row.col.f32.bf16.bf16.f32 "
        "{%0,%1,%2,%3},{%4,%5,%6,%7},{%8,%9},{%0,%1,%2,%3};"
        : "+f"(c[0]), "+f"(c[1]), "+f"(c[2]), "+f"(c[3])
        : "r"(a0), "r"(a1), "r"(a2), "r"(a3), "r"(b0), "r"(b1));
}

// ---------------- prep: A [BT,32] fp32 -> [BT,64] bf16 hi|lo ----------------
__global__ __launch_bounds__(256)
void prep_a(const float* __restrict__ X, __nv_bfloat16* __restrict__ O) {
    int r = blockIdx.x * 256 + threadIdx.x;
    const float4* src = (const float4*)(X + (size_t)r * 32);
    uint32_t hi[8], lo[8];
    #pragma unroll
    for (int q = 0; q < 8; q++) {
        float4 v = src[q];
        float f[4] = {v.x, v.y, v.z, v.w};
        unsigned short h[4], l[4];
        #pragma unroll
        for (int e = 0; e < 4; e++) {
            __nv_bfloat16 hb = __float2bfloat16(f[e]);
            __nv_bfloat16 lb = __float2bfloat16(f[e] - __bfloat162float(hb));
            h[e] = __bfloat16_as_ushort(hb);
            l[e] = __bfloat16_as_ushort(lb);
        }
        hi[q] = (uint32_t)h[0] | ((uint32_t)h[1] << 16);   // wait: q covers 4 floats = 2 uint32
        lo[q] = (uint32_t)l[0] | ((uint32_t)l[1] << 16);
        // pack second pair into next slot via shift below
        hi[q] = hi[q]; lo[q] = lo[q];
        // store both pairs explicitly:
        ((uint32_t*)(O + (size_t)r * 64))[q * 2 + 0] = (uint32_t)h[0] | ((uint32_t)h[1] << 16);
        ((uint32_t*)(O + (size_t)r * 64))[q * 2 + 1] = (uint32_t)h[2] | ((uint32_t)h[3] << 16);
        ((uint32_t*)(O + (size_t)r * 64 + 32))[q * 2 + 0] = (uint32_t)l[0] | ((uint32_t)l[1] << 16);
        ((uint32_t*)(O + (size_t)r * 64 + 32))[q * 2 + 1] = (uint32_t)l[2] | ((uint32_t)l[3] << 16);
    }
}

// ---------------- prep: W [32,N] -> [N,96] bf16 [wh|wh|wl] ----------------
__global__ void prep_w(const float* __restrict__ W, int N, __nv_bfloat16* __restrict__ O) {
    int n = blockIdx.x * blockDim.x + threadIdx.x;
    if (n >= N) return;
    #pragma unroll 8
    for (int k = 0; k < 32; k++) {
        float v = W[(size_t)k * N + n];
        __nv_bfloat16 hb = __float2bfloat16(v);
        __nv_bfloat16 lb = __float2bfloat16(v - __bfloat162float(hb));
        O[(size_t)n * 96 + k]      = hb;
        O[(size_t)n * 96 + 32 + k] = hb;
        O[(size_t)n * 96 + 64 + k] = lb;
    }
}

// ---------------- Phase 1: mma.sync GEMM + bias + group(64) softmax ----------------
// CTA: 256 threads (8 warps). Tile M=128 (rows=bt), N=64 (one softmax group).
// Warp w handles rows 16w..16w+15 x all 64 cols. K_eff = 96 (hi/lo split).
__global__ __launch_bounds__(256)
void mma_softmax(const __nv_bfloat16* __restrict__ gA,  // [BT,64]
                 const __nv_bfloat16* __restrict__ gB,  // [N,96]
                 const float* __restrict__ bias,        // [N]
                 float* __restrict__ out,               // [BT,N]
                 int N)
{
    __shared__ __align__(16) __nv_bfloat16 Asm[128][72];   // 144B stride
    __shared__ __align__(16) __nv_bfloat16 Bsm[64][104];   // 208B stride

    const int tid = threadIdx.x;
    const int w   = tid >> 5;
    const int l   = tid & 31;
    const int g   = l >> 2;
    const int t   = l & 3;
    const int row0 = blockIdx.y * 128;
    const int n0   = blockIdx.x * 64;

    // A tile: 128 rows x 64 halves = 8 x 16B chunks/row -> 1024 chunks
    #pragma unroll
    for (int q = 0; q < 4; q++) {
        int i = q * 256 + tid;
        int r = i >> 3;
        int c = (i & 7) * 8;
        cpasync16(smem_u32(&Asm[r][c]), gA + (size_t)(row0 + r) * 64 + c);
    }
    // B tile: 64 rows x 96 halves = 12 x 16B chunks/row -> 768 chunks
    #pragma unroll
    for (int q = 0; q < 3; q++) {
        int i = q * 256 + tid;
        int r = i / 12;
        int c = (i % 12) * 8;
        cpasync16(smem_u32(&Bsm[r][c]), gB + (size_t)(n0 + r) * 96 + c);
    }
    CP_COMMIT();
    CP_WAIT0();
    __syncthreads();

    float acc[8][4];
    #pragma unroll
    for (int nt = 0; nt < 8; nt++)
        #pragma unroll
        for (int e = 0; e < 4; e++) acc[nt][e] = 0.0f;

    #pragma unroll
    for (int s = 0; s < 6; s++) {
        const int ab = (s < 4 ? 16 * s : 16 * (s - 4)) + 2 * t;   // A column base
        const int bb = 16 * s + 2 * t;                            // B column base
        uint32_t a0 = *(const uint32_t*)&Asm[16 * w + g][ab];
        uint32_t a1 = *(const uint32_t*)&Asm[16 * w + g + 8][ab];
        uint32_t a2 = *(const uint32_t*)&Asm[16 * w + g][ab + 8];
        uint32_t a3 = *(const uint32_t*)&Asm[16 * w + g + 8][ab + 8];
        #pragma unroll
        for (int nt = 0; nt < 8; nt++) {
            uint32_t b0 = *(const uint32_t*)&Bsm[8 * nt + g][bb];
            uint32_t b1 = *(const uint32_t*)&Bsm[8 * nt + g][bb + 8];
            mma16816(acc[nt], a0, a1, a2, a3, b0, b1);
        }
    }

    // Epilogue. Thread owns cols {8nt+2t, 8nt+2t+1} for rows r0=row0+16w+g and r1=r0+8.
    float sum0 = 0.0f, sum1 = 0.0f;
    #pragma unroll
    for (int nt = 0; nt < 8; nt++) {
        float2 bv = *(const float2*)(bias + n0 + 8 * nt + 2 * t);
        acc[nt][0] = __expf(acc[nt][0] + bv.x);
        acc[nt][1] = __expf(acc[nt][1] + bv.y);
        acc[nt][2] = __expf(acc[nt][2] + bv.x);
        acc[nt][3] = __expf(acc[nt][3] + bv.y);
        sum0 += acc[nt][0] + acc[nt][1];
        sum1 += acc[nt][2] + acc[nt][3];
    }
    // reduce across the quad (t = 0..3) -> full 64-col softmax sums
    sum0 += __shfl_xor_sync(0xffffffffu, sum0, 1);
    sum0 += __shfl_xor_sync(0xffffffffu, sum0, 2);
    sum1 += __shfl_xor_sync(0xffffffffu, sum1, 1);
    sum1 += __shfl_xor_sync(0xffffffffu, sum1, 2);
    float ri0 = 1.0f / sum0;
    float ri1 = 1.0f / sum1;

    float* o0 = out + (size_t)(row0 + 16 * w + g) * N + n0 + 2 * t;
    float* o1 = out + (size_t)(row0 + 16 * w + g + 8) * N + n0 + 2 * t;
    #pragma unroll
    for (int nt = 0; nt < 8; nt++) {
        *(float2*)(o0 + 8 * nt) = make_float2(acc[nt][0] * ri0, acc[nt][1] * ri0);
        *(float2*)(o1 + 8 * nt) = make_float2(acc[nt][2] * ri1, acc[nt][3] * ri1);
    }
}

// ---------------- Phase 2: per-batch recurrence (HBM-bound) ----------------
__global__ __launch_bounds__(256, 2)
void recur_kernel(const float* __restrict__ xm,   // [B,T,8]
                  const float* __restrict__ xa,   // [B,T,32]
                  const float* __restrict__ Wo,   // [32,64]
                  const float* __restrict__ bo,   // [64]
                  const float* __restrict__ Wfc,  // [64,1]
                  const float* __restrict__ bfc,  // [1]
                  float* __restrict__ d_out,
                  int out_size)
{
    const int b   = blockIdx.x;
    const int tid = threadIdx.x;

    __shared__ __align__(16) float rbuf[2][4096];
    __shared__ __align__(16) float jbuf[2][512];
    __shared__ __align__(16) float mbuf[2][8];
    __shared__ float c_s[64];
    __shared__ float psum[256];
    __shared__ float xa_s[32];

    if (tid < 64) c_s[tid] = 0.0f;
    if (tid < 32) xa_s[tid] = xa[((size_t)b * TT + (TT - 1)) * AUXD + tid];

    {
        const float* rsrc = g_r + ((size_t)(b * TT + 0) << 12);
        #pragma unroll
        for (int q = 0; q < 4; q++)
            cpasync16(smem_u32(&rbuf[0][q * 1024 + tid * 4]), rsrc + q * 1024 + tid * 4);
        if (tid < 128) {
            const float* jsrc = g_j + ((size_t)(b * TT + 0) << 9);
            cpasync16(smem_u32(&jbuf[0][tid * 4]), jsrc + tid * 4);
        }
        if (tid < 2) {
            const float* msrc = xm + ((size_t)(b * TT + 0) << 3);
            cpasync16(smem_u32(&mbuf[0][tid * 4]), msrc + tid * 4);
        }
    }
    CP_COMMIT();

    const int k = tid & 63;
    const int p = tid >> 6;

    for (int t = 0; t < TT; t++) {
        const int s = t & 1;
        if (t + 1 < TT) {
            const int s2 = (t + 1) & 1;
            const float* rsrc = g_r + ((size_t)(b * TT + t + 1) << 12);
            #pragma unroll
            for (int q = 0; q < 4; q++)
                cpasync16(smem_u32(&rbuf[s2][q * 1024 + tid * 4]), rsrc + q * 1024 + tid * 4);
            if (tid < 128) {
                const float* jsrc = g_j + ((size_t)(b * TT + t + 1) << 9);
                cpasync16(smem_u32(&jbuf[s2][tid * 4]), jsrc + tid * 4);
            }
            if (tid < 2) {
                const float* msrc = xm + ((size_t)(b * TT + t + 1) << 3);
                cpasync16(smem_u32(&mbuf[s2][tid * 4]), msrc + tid * 4);
            }
        }
        CP_COMMIT();
        CP_WAIT1();
        __syncthreads();

        const float* rs = rbuf[s];
        float acc = 0.0f;
        #pragma unroll
        for (int hh = 0; hh < 16; hh++) {
            int h = 16 * p + hh;
            acc += c_s[h] * rs[h * 64 + k];
        }
        psum[tid] = acc;
        __syncthreads();

        if (tid < 64) {
            float m_in = 0.0f;
            #pragma unroll
            for (int m = 0; m < 8; m++)
                m_in += mbuf[s][m] * jbuf[s][m * 64 + k];
            float cn = m_in + psum[k] + psum[64 + k] + psum[128 + k] + psum[192 + k];
            c_s[k] = cn;
        }
        __syncthreads();
    }

    if (tid < 64) {
        float dot = bo[tid];
        #pragma unroll
        for (int a = 0; a < 32; a++)
            dot += xa_s[a] * Wo[a * 64 + tid];
        float o = 1.0f / (1.0f + __expf(-dot));
        float aout = o * c_s[tid];
        float v = aout * Wfc[tid];
        v += __shfl_xor_sync(0xffffffffu, v, 16);
        v += __shfl_xor_sync(0xffffffffu, v, 8);
        v += __shfl_xor_sync(0xffffffffu, v, 4);
        v += __shfl_xor_sync(0xffffffffu, v, 2);
        v += __shfl_xor_sync(0xffffffffu, v, 1);
        if ((tid & 31) == 0) psum[tid >> 5] = v;
    }
    __syncthreads();

    if (tid == 0) d_out[b] = psum[0] + psum[1] + bfc[0];
    if (tid < 64 && out_size >= BB + BB * HH)
        d_out[BB + b * HH + tid] = c_s[tid];   // c_final
}

// ---------------- launch ----------------
extern "C" void kernel_launch(void* const* d_in, const int* in_sizes, int n_in,
                              void* d_out, int out_size) {
    const float* x_m = (const float*)d_in[0];
    const float* x_a = (const float*)d_in[1];
    const float* Wj  = (const float*)d_in[2];
    const float* bj  = (const float*)d_in[3];
    const float* Wr  = (const float*)d_in[4];
    const float* br  = (const float*)d_in[5];
    const float* Wo  = (const float*)d_in[6];
    const float* bo  = (const float*)d_in[7];
    const float* Wfc = (const float*)d_in[8];
    const float* bfc = (const float*)d_in[9];
    float* out = (float*)d_out;

    void *pj, *pr, *pa, *pbr, *pbj;
    cudaGetSymbolAddress(&pj, g_j);
    cudaGetSymbolAddress(&pr, g_r);
    cudaGetSymbolAddress(&pa, g_a);
    cudaGetSymbolAddress(&pbr, g_br);
    cudaGetSymbolAddress(&pbj, g_bj);

    // build bf16-split images
    prep_a<<<BT / 256, 256>>>(x_a, (__nv_bfloat16*)pa);
    prep_w<<<16, 256>>>(Wr, 4096, (__nv_bfloat16*)pbr);
    prep_w<<<2, 256>>>(Wj, 512, (__nv_bfloat16*)pbj);

    // j: softmax((xa @ Wj + bj) grouped by 64) -> g_j [BT,512]
    mma_softmax<<<dim3(512 / 64, BT / 128), 256>>>(
        (const __nv_bfloat16*)pa, (const __nv_bfloat16*)pbj, bj, (float*)pj, 512);
    // r: softmax((xa @ Wr + br) grouped by 64) -> g_r [BT,4096]
    mma_softmax<<<dim3(4096 / 64, BT / 128), 256>>>(
        (const __nv_bfloat16*)pa, (const __nv_bfloat16*)pbr, br, (float*)pr, 4096);
    // scan
    recur_kernel<<<BB, 256>>>(x_m, x_a, Wo, bo, Wfc, bfc, out, out_size);
}